// round 1
// baseline (speedup 1.0000x reference)
#include <cuda_runtime.h>

// PixelContrastLoss fused kernel, fp32 SIMT baseline.
// Shapes (fixed by problem): B=64 classes, n_view=128, D=128 -> N=8192.

#define NCLS   64
#define NVIEW  128
#define DIM    128
#define NROWS  8192          // NCLS * NVIEW
#define BM     64
#define BN     64
#define LDA    132           // padded row stride (floats), multiple of 4 for float4 STS
#define NBLK   (NROWS / BM)  // 128
#define SMEM_BYTES (2 * BM * LDA * 4)

__device__ float4 g_feat[NROWS * (DIM / 4)];   // normalized features
__device__ float  g_partial[NBLK];             // per-block loss sums

// ---------------------------------------------------------------------------
// K1: L2-normalize rows. One warp per row, one float4 per lane.
// ---------------------------------------------------------------------------
__global__ void __launch_bounds__(256) normalize_kernel(const float* __restrict__ x) {
    int warp = threadIdx.x >> 5;
    int lane = threadIdx.x & 31;
    int row  = blockIdx.x * 8 + warp;
    const float4* xr = reinterpret_cast<const float4*>(x) + row * (DIM / 4);
    float4 v = xr[lane];
    float ss = v.x * v.x + v.y * v.y + v.z * v.z + v.w * v.w;
#pragma unroll
    for (int m = 16; m; m >>= 1) ss += __shfl_xor_sync(0xffffffffu, ss, m);
    float inv = 1.0f / fmaxf(sqrtf(ss), 1e-12f);
    v.x *= inv; v.y *= inv; v.z *= inv; v.w *= inv;
    g_feat[row * (DIM / 4) + lane] = v;
}

// ---------------------------------------------------------------------------
// K2: fused sim-GEMM + masked exp-sums + per-row loss.
// Block: 256 threads (16x16), tile BM=64 rows x (loop over) all 8192 cols.
// Thread (tx,ty) owns rows {ty+16r} and cols {tx+16c}, r,c in 0..3.
// Shift: exp(s - 1.0) -- exact row-max is 1 +/- fp eps (diag of normalized
// Gram); the pos/(tot+eps) ratio is shift-invariant to ~1e-12.
// ---------------------------------------------------------------------------
__global__ void __launch_bounds__(256) pcl_main_kernel(const int* __restrict__ y) {
    extern __shared__ float smem[];
    float* As = smem;                 // [BM][LDA]
    float* Bs = smem + BM * LDA;      // [BN][LDA]

    int tid = threadIdx.x;
    int tx = tid & 15;
    int ty = tid >> 4;
    int i0 = blockIdx.x * BM;

    int rlab[4], clab[4];
#pragma unroll
    for (int r = 0; r < 4; r++) rlab[r] = y[(i0 + ty + 16 * r) >> 7];
    // col label of local col t is y[(j0+t) & 63] = y[t] since j0 % 64 == 0
#pragma unroll
    for (int c = 0; c < 4; c++) clab[c] = y[tx + 16 * c];

    // Load A tile (64 x 128) once, padded stride
    for (int f = tid; f < BM * (DIM / 4); f += 256) {
        int row = f >> 5, k4 = f & 31;
        float4 v = g_feat[(i0 + row) * (DIM / 4) + k4];
        *reinterpret_cast<float4*>(&As[row * LDA + k4 * 4]) = v;
    }

    float pos[4] = {0.f, 0.f, 0.f, 0.f};
    float tot[4] = {0.f, 0.f, 0.f, 0.f};

    for (int j0 = 0; j0 < NROWS; j0 += BN) {
        __syncthreads();  // protect Bs from previous iteration's readers
        for (int f = tid; f < BN * (DIM / 4); f += 256) {
            int row = f >> 5, k4 = f & 31;
            *reinterpret_cast<float4*>(&Bs[row * LDA + k4 * 4]) =
                g_feat[(j0 + row) * (DIM / 4) + k4];
        }
        __syncthreads();

        float acc[4][4];
#pragma unroll
        for (int r = 0; r < 4; r++)
#pragma unroll
            for (int c = 0; c < 4; c++) acc[r][c] = 0.f;

        for (int kk = 0; kk < DIM; kk += 4) {
            float4 a4[4], b4[4];
#pragma unroll
            for (int r = 0; r < 4; r++)
                a4[r] = *reinterpret_cast<const float4*>(&As[(ty + 16 * r) * LDA + kk]);
#pragma unroll
            for (int c = 0; c < 4; c++)
                b4[c] = *reinterpret_cast<const float4*>(&Bs[(tx + 16 * c) * LDA + kk]);
#pragma unroll
            for (int r = 0; r < 4; r++) {
#pragma unroll
                for (int c = 0; c < 4; c++) {
                    acc[r][c] = fmaf(a4[r].x, b4[c].x, acc[r][c]);
                    acc[r][c] = fmaf(a4[r].y, b4[c].y, acc[r][c]);
                    acc[r][c] = fmaf(a4[r].z, b4[c].z, acc[r][c]);
                    acc[r][c] = fmaf(a4[r].w, b4[c].w, acc[r][c]);
                }
            }
        }

#pragma unroll
        for (int r = 0; r < 4; r++) {
#pragma unroll
            for (int c = 0; c < 4; c++) {
                float e = __expf(acc[r][c] - 1.0f);
                tot[r] += e;
                pos[r] += (rlab[r] == clab[c]) ? e : 0.0f;
            }
        }
    }

    // Reduce pos/tot across the 16 tx threads (tx = low 4 bits of lane id)
#pragma unroll
    for (int m = 1; m < 16; m <<= 1) {
#pragma unroll
        for (int r = 0; r < 4; r++) {
            pos[r] += __shfl_xor_sync(0xffffffffu, pos[r], m);
            tot[r] += __shfl_xor_sync(0xffffffffu, tot[r], m);
        }
    }

    __syncthreads();  // all compute done; safe to reuse smem
    if (tx == 0) {
        float s = 0.f;
#pragma unroll
        for (int r = 0; r < 4; r++) {
            float ratio = pos[r] / (tot[r] + 1e-8f);  // pos+neg == tot
            s += -logf(ratio + 1e-8f);
        }
        smem[ty] = s;
    }
    __syncthreads();
    if (tid == 0) {
        float s = 0.f;
#pragma unroll
        for (int t = 0; t < 16; t++) s += smem[t];
        g_partial[blockIdx.x] = s;
    }
}

// ---------------------------------------------------------------------------
// K3: reduce 128 partials -> mean
// ---------------------------------------------------------------------------
__global__ void __launch_bounds__(128) finalize_kernel(float* __restrict__ out) {
    __shared__ float sm[4];
    int t = threadIdx.x;
    float v = g_partial[t];
#pragma unroll
    for (int m = 16; m; m >>= 1) v += __shfl_xor_sync(0xffffffffu, v, m);
    if ((t & 31) == 0) sm[t >> 5] = v;
    __syncthreads();
    if (t == 0) {
        float s = sm[0] + sm[1] + sm[2] + sm[3];
        out[0] = s / (float)NROWS;
    }
}

// ---------------------------------------------------------------------------
extern "C" void kernel_launch(void* const* d_in, const int* in_sizes, int n_in,
                              void* d_out, int out_size) {
    const float* x = (const float*)d_in[0];   // [64,128,128] f32
    const int*   y = (const int*)d_in[1];     // [64] i32
    float* out = (float*)d_out;

    cudaFuncSetAttribute(pcl_main_kernel,
                         cudaFuncAttributeMaxDynamicSharedMemorySize, SMEM_BYTES);

    normalize_kernel<<<NROWS / 8, 256>>>(x);
    pcl_main_kernel<<<NBLK, 256, SMEM_BYTES>>>(y);
    finalize_kernel<<<1, 128>>>(out);
}

// round 3
// speedup vs baseline: 3.5182x; 3.5182x over previous
#include <cuda_runtime.h>
#include <cuda_fp16.h>
#include <cstdint>

// ============================================================================
// PixelContrastLoss — mma.sync (HMMA) fp16-split Gram kernel, base sm_100.
// sim = feat@feat^T via hi*hi + lo*hi + hi*lo   (fp16 split, fp32 accum)
// N = 8192 rows, D = 128.
// ============================================================================

#define NROWS 8192
#define DIM   128
#define TM    128
#define TN    128
#define NJT   32            // j-tiles per CTA (covers 4096 cols)
#define ROWB  256           // bytes per row (128 fp16)
#define TILEB 32768         // 128 rows * 256 B

// smem layout
#define SM_AHI 0
#define SM_ALO TILEB
#define SM_B   (2*TILEB)    // 4 tiles: [buf0 hi, buf0 lo, buf1 hi, buf1 lo]
#define SMEM_TOTAL (6*TILEB)   // 196608 B

__device__ __align__(128) unsigned char g_hi[NROWS * ROWB];  // 2 MB
__device__ __align__(128) unsigned char g_lo[NROWS * ROWB];  // 2 MB
__device__ float g_pp[2][2][NROWS];
__device__ float g_pt[2][2][NROWS];

// ---------------------------------------------------------------------------
__device__ __forceinline__ uint32_t su32(const void* p) {
    uint32_t a;
    asm("{ .reg .u64 t; cvta.to.shared.u64 t, %1; cvt.u32.u64 %0, t; }"
        : "=r"(a) : "l"(p));
    return a;
}
__device__ __forceinline__ void cp16(uint32_t d, const void* s) {
    asm volatile("cp.async.cg.shared.global [%0], [%1], 16;" :: "r"(d), "l"(s));
}
#define CP_COMMIT() asm volatile("cp.async.commit_group;" ::: "memory")
#define CP_WAIT1()  asm volatile("cp.async.wait_group 1;" ::: "memory")

__device__ __forceinline__ void ldsm4(uint32_t* r, uint32_t addr) {
    asm volatile("ldmatrix.sync.aligned.m8n8.x4.shared.b16 {%0,%1,%2,%3}, [%4];"
                 : "=r"(r[0]), "=r"(r[1]), "=r"(r[2]), "=r"(r[3]) : "r"(addr));
}
__device__ __forceinline__ void mma16816(float* c, const uint32_t* a,
                                         const uint32_t* b) {
    asm volatile(
        "mma.sync.aligned.m16n8k16.row.col.f32.f16.f16.f32 "
        "{%0,%1,%2,%3}, {%4,%5,%6,%7}, {%8,%9}, {%0,%1,%2,%3};"
        : "+f"(c[0]), "+f"(c[1]), "+f"(c[2]), "+f"(c[3])
        : "r"(a[0]), "r"(a[1]), "r"(a[2]), "r"(a[3]), "r"(b[0]), "r"(b[1]));
}

// ---------------------------------------------------------------------------
// K1: normalize rows, split fp32 -> (hi, lo) fp16, write SW128-swizzled
// K-major layout: 8-row groups of 2048 B (two 1024-B atoms per group).
// ---------------------------------------------------------------------------
__global__ void __launch_bounds__(256) normalize_split_kernel(const float* __restrict__ x) {
    int warp = threadIdx.x >> 5, lane = threadIdx.x & 31;
    int row  = blockIdx.x * 8 + warp;
    const float4* xr = reinterpret_cast<const float4*>(x) + row * 32;
    float4 v = xr[lane];
    float ss = v.x * v.x + v.y * v.y + v.z * v.z + v.w * v.w;
#pragma unroll
    for (int m = 16; m; m >>= 1) ss += __shfl_xor_sync(0xffffffffu, ss, m);
    float inv = 1.0f / fmaxf(sqrtf(ss), 1e-12f);
    float f[4] = {v.x * inv, v.y * inv, v.z * inv, v.w * inv};

    unsigned short hb[4], lb[4];
#pragma unroll
    for (int i = 0; i < 4; i++) {
        __half h = __float2half_rn(f[i]);
        float hf = __half2float(h);
        __half l = __float2half_rn(f[i] - hf);
        hb[i] = *reinterpret_cast<unsigned short*>(&h);
        lb[i] = *reinterpret_cast<unsigned short*>(&l);
    }
    uint2 uhi, ulo;
    uhi.x = (uint32_t)hb[0] | ((uint32_t)hb[1] << 16);
    uhi.y = (uint32_t)hb[2] | ((uint32_t)hb[3] << 16);
    ulo.x = (uint32_t)lb[0] | ((uint32_t)lb[1] << 16);
    ulo.y = (uint32_t)lb[2] | ((uint32_t)lb[3] << 16);

    int g = row >> 3, r = row & 7;
    int c0 = lane << 2;                        // f16 col, multiple of 4
    uint32_t off = (uint32_t)((c0 >> 6) * 1024 + r * 128 + (c0 & 63) * 2);
    off ^= (off >> 3) & 0x70;                  // SW128 swizzle
    size_t addr = (size_t)g * 2048 + off;
    *reinterpret_cast<uint2*>(g_hi + addr) = uhi;
    *reinterpret_cast<uint2*>(g_lo + addr) = ulo;
}

// ---------------------------------------------------------------------------
// K2: pipelined HMMA Gram + fused masked exp-sums.
// grid = 128: itile = bx>>1 (128 rows), j-half = bx&1 (4096 cols).
// 8 warps: (wm = wid&3) x (wn = wid>>2); warp tile 32(M) x 64(N).
// ---------------------------------------------------------------------------
__global__ void __launch_bounds__(256) pcl_mma_kernel(const int* __restrict__ y) {
    extern __shared__ unsigned char smem[];
    uint32_t sb = su32(smem);
    int tid = threadIdx.x, lane = tid & 31, wid = tid >> 5;
    int wm = wid & 3, wn = wid >> 2;
    int bx = blockIdx.x, itile = bx >> 1, jg = bx & 1;
    int i0 = itile * TM;
    int jbase = jg * (NROWS / 2);

    // ---- prologue loads: A tiles + B0, B1 (groups G0, G1) ----
    {
        const unsigned char* ah = g_hi + (size_t)i0 * ROWB;
        const unsigned char* al = g_lo + (size_t)i0 * ROWB;
        for (int t = tid; t < 2048; t += 256) {
            cp16(sb + SM_AHI + t * 16, ah + t * 16);
            cp16(sb + SM_ALO + t * 16, al + t * 16);
        }
        const unsigned char* b0h = g_hi + (size_t)jbase * ROWB;
        const unsigned char* b0l = g_lo + (size_t)jbase * ROWB;
        for (int t = tid; t < 2048; t += 256) {
            cp16(sb + SM_B + t * 16, b0h + t * 16);
            cp16(sb + SM_B + TILEB + t * 16, b0l + t * 16);
        }
        CP_COMMIT();
        const unsigned char* b1h = g_hi + (size_t)(jbase + TN) * ROWB;
        const unsigned char* b1l = g_lo + (size_t)(jbase + TN) * ROWB;
        for (int t = tid; t < 2048; t += 256) {
            cp16(sb + SM_B + 2 * TILEB + t * 16, b1h + t * 16);
            cp16(sb + SM_B + 3 * TILEB + t * 16, b1l + t * 16);
        }
        CP_COMMIT();
    }

    // ---- per-thread constants ----
    int t4 = lane & 3, g4 = lane >> 2;
    int rlab = y[itile];                       // all 128 rows share one label
    bool mk0[8], mk1[8];
#pragma unroll
    for (int nb = 0; nb < 8; nb++) {
        mk0[nb] = (y[nb * 8 + 2 * t4]     == rlab);
        mk1[nb] = (y[nb * 8 + 2 * t4 + 1] == rlab);
    }
    int aRow[2], bRow[4];
#pragma unroll
    for (int mb = 0; mb < 2; mb++) {
        int ar = wm * 32 + mb * 16 + (lane & 15);
        aRow[mb] = (ar >> 3) * 2048 + (ar & 7) * 128;
    }
#pragma unroll
    for (int np = 0; np < 4; np++) {
        int br = wn * 64 + np * 16 + ((lane >> 4) << 3) + (lane & 7);
        bRow[np] = (br >> 3) * 2048 + (br & 7) * 128;
    }
    int swz = (lane & 7) << 4;
    int aC = (lane >> 4) * 16;
    int bC = ((lane >> 3) & 1) * 16;

    float pos[4] = {0.f, 0.f, 0.f, 0.f};
    float tot[4] = {0.f, 0.f, 0.f, 0.f};

    for (int jt = 0; jt < NJT; jt++) {
        CP_WAIT1();
        __syncthreads();                       // B[jt] (and A) visible to all

        uint32_t Ah = sb + SM_AHI, Al = sb + SM_ALO;
        uint32_t Bh = sb + SM_B + ((jt & 1) * 2) * TILEB;
        uint32_t Bl = Bh + TILEB;

        float acc[2][8][4];
#pragma unroll
        for (int mb = 0; mb < 2; mb++)
#pragma unroll
            for (int nb = 0; nb < 8; nb++)
#pragma unroll
                for (int k = 0; k < 4; k++) acc[mb][nb][k] = 0.f;

#pragma unroll
        for (int pass = 0; pass < 3; pass++) {
            uint32_t Ab = (pass == 1) ? Al : Ah;
            uint32_t Bb = (pass == 2) ? Bl : Bh;
#pragma unroll
            for (int ks = 0; ks < 8; ks++) {
                uint32_t areg[2][4], breg[16];
                int bcA = ks * 32 + aC;
                int offA = ((bcA >> 7) << 10) + ((bcA & 127) ^ swz);
                ldsm4(areg[0], Ab + aRow[0] + offA);
                ldsm4(areg[1], Ab + aRow[1] + offA);
                int bcB = ks * 32 + bC;
                int offB = ((bcB >> 7) << 10) + ((bcB & 127) ^ swz);
#pragma unroll
                for (int np = 0; np < 4; np++)
                    ldsm4(&breg[np * 4], Bb + bRow[np] + offB);
#pragma unroll
                for (int mb = 0; mb < 2; mb++)
#pragma unroll
                    for (int nb = 0; nb < 8; nb++)
                        mma16816(acc[mb][nb], areg[mb], &breg[nb * 2]);
            }
        }

        __syncthreads();                       // done reading B[jt] buffer
        if (jt + 2 < NJT) {                    // prefetch B[jt+2] into buf jt&1
            const unsigned char* bh = g_hi + (size_t)(jbase + (jt + 2) * TN) * ROWB;
            const unsigned char* bl = g_lo + (size_t)(jbase + (jt + 2) * TN) * ROWB;
            uint32_t dst = sb + SM_B + ((jt & 1) * 2) * TILEB;
            for (int t = tid; t < 2048; t += 256) {
                cp16(dst + t * 16, bh + t * 16);
                cp16(dst + TILEB + t * 16, bl + t * 16);
            }
        }
        CP_COMMIT();                           // one group per iteration, always

        // ---- epilogue: exp + masked accumulate (register-only) ----
#pragma unroll
        for (int mb = 0; mb < 2; mb++) {
#pragma unroll
            for (int nb = 0; nb < 8; nb++) {
                float e0 = __expf(acc[mb][nb][0] - 1.0f);
                float e1 = __expf(acc[mb][nb][1] - 1.0f);
                float e2 = __expf(acc[mb][nb][2] - 1.0f);
                float e3 = __expf(acc[mb][nb][3] - 1.0f);
                tot[mb * 2 + 0] += e0 + e1;
                tot[mb * 2 + 1] += e2 + e3;
                if (mk0[nb]) { pos[mb * 2] += e0; pos[mb * 2 + 1] += e2; }
                if (mk1[nb]) { pos[mb * 2] += e1; pos[mb * 2 + 1] += e3; }
            }
        }
    }

    // reduce over the 4 lanes sharing each row (lane ^ 1, lane ^ 2)
#pragma unroll
    for (int m = 1; m < 4; m <<= 1) {
#pragma unroll
        for (int i = 0; i < 4; i++) {
            pos[i] += __shfl_xor_sync(0xffffffffu, pos[i], m);
            tot[i] += __shfl_xor_sync(0xffffffffu, tot[i], m);
        }
    }
    if ((lane & 3) == 0) {
#pragma unroll
        for (int mb = 0; mb < 2; mb++) {
            int r0 = i0 + wm * 32 + mb * 16 + g4;
            g_pp[jg][wn][r0]     = pos[mb * 2];
            g_pt[jg][wn][r0]     = tot[mb * 2];
            g_pp[jg][wn][r0 + 8] = pos[mb * 2 + 1];
            g_pt[jg][wn][r0 + 8] = tot[mb * 2 + 1];
        }
    }
}

// ---------------------------------------------------------------------------
// K3: per-row loss, mean over 8192 rows
// ---------------------------------------------------------------------------
__global__ void __launch_bounds__(1024) finalize_kernel(float* __restrict__ out) {
    __shared__ float sm[32];
    int tid = threadIdx.x;
    float s = 0.f;
#pragma unroll
    for (int rr = 0; rr < NROWS / 1024; rr++) {
        int r = tid + rr * 1024;
        float pos = g_pp[0][0][r] + g_pp[0][1][r] + g_pp[1][0][r] + g_pp[1][1][r];
        float tot = g_pt[0][0][r] + g_pt[0][1][r] + g_pt[1][0][r] + g_pt[1][1][r];
        s += -logf(pos / (tot + 1e-8f) + 1e-8f);
    }
#pragma unroll
    for (int m = 16; m; m >>= 1) s += __shfl_xor_sync(0xffffffffu, s, m);
    if ((tid & 31) == 0) sm[tid >> 5] = s;
    __syncthreads();
    if (tid < 32) {
        float v = sm[tid];
#pragma unroll
        for (int m = 16; m; m >>= 1) v += __shfl_xor_sync(0xffffffffu, v, m);
        if (tid == 0) out[0] = v / (float)NROWS;
    }
}

// ---------------------------------------------------------------------------
extern "C" void kernel_launch(void* const* d_in, const int* in_sizes, int n_in,
                              void* d_out, int out_size) {
    const float* x = (const float*)d_in[0];   // [64,128,128] f32
    const int*   y = (const int*)d_in[1];     // [64] i32
    float* out = (float*)d_out;

    cudaFuncSetAttribute(pcl_mma_kernel,
                         cudaFuncAttributeMaxDynamicSharedMemorySize, SMEM_TOTAL);

    normalize_split_kernel<<<NROWS / 8, 256>>>(x);
    pcl_mma_kernel<<<128, 256, SMEM_TOTAL>>>(y);
    finalize_kernel<<<1, 1024>>>(out);
}